// round 17
// baseline (speedup 1.0000x reference)
#include <cuda_runtime.h>
#include <cuda_fp16.h>
#include <cstdint>

// RoutingLinear == GEMM + bias: O[t][v] = sum_d X[t][d]*W[v][d] + b[v]
// X[2048,4096] fp32, W[32000,4096] fp32, b[32000], O[2048,32000] fp32.
//
// R16 (1710.8us) showed the plateau had a non-tensor component: warp tile
// 32x64 @ 4 warps/CTA cut LDSM/issue per MAC 25% -> GEMM ~97% of the
// rt~13 HMMA floor. R17 delta (single change): hoist BOTH ks fragment-load
// groups to the top of each k-iteration so 8 independent LDSM.x4 issue
// before the 64 HMMAs — scheduler overlaps LDS latency under tensor work.
// Regs: acc 64 + af 16 + bf 32 + misc ~= 135 < 170 budget (3 CTA/SM).

#define NTHR 128
#define BM 128
#define BN 64
#define BK 32
#define STAGES 4
#define TS 40                         // smem row stride in halfs (32 + 8 pad)
#define TILE_A_BYTES (BM * TS * 2)    // 10240
#define TILE_B_BYTES (BN * TS * 2)    // 5120
#define STAGE_BYTES (TILE_A_BYTES + TILE_B_BYTES)  // 15360
#define SMEM_NEED (STAGES * STAGE_BYTES)           // 61440 -> 3 CTAs/SM

#define CNVT 256                      // conv kernels keep 256 threads
#define T_MAX 2048
#define D_MAX 4096
#define V_MAX 32000

// ---------------- scratch (static device memory; no allocs allowed) ----------
__device__ __half g_Xh[(size_t)T_MAX * D_MAX];
__device__ __half g_Wh[(size_t)V_MAX * D_MAX];

// ---------------- helpers -----------------------------------------------------
__device__ __forceinline__ uint32_t smem_u32_of(const void* p) {
    uint32_t a;
    asm("{ .reg .u64 t; cvta.to.shared.u64 t, %1; cvt.u32.u64 %0, t; }"
        : "=r"(a) : "l"(p));
    return a;
}
__device__ __forceinline__ void cp_async16(uint32_t dst, const void* src) {
    asm volatile("cp.async.cg.shared.global [%0], [%1], 16;"
                 :: "r"(dst), "l"(src) : "memory");
}
__device__ __forceinline__ void ldmatrix_x4(uint32_t& r0, uint32_t& r1,
                                            uint32_t& r2, uint32_t& r3,
                                            uint32_t addr) {
    asm volatile("ldmatrix.sync.aligned.m8n8.x4.shared.b16 {%0,%1,%2,%3}, [%4];"
                 : "=r"(r0), "=r"(r1), "=r"(r2), "=r"(r3) : "r"(addr));
}
__device__ __forceinline__ void mma_f16(float* d, const uint32_t* a,
                                        const uint32_t* b) {
    asm volatile(
        "mma.sync.aligned.m16n8k16.row.col.f32.f16.f16.f32 "
        "{%0,%1,%2,%3}, {%4,%5,%6,%7}, {%8,%9}, {%0,%1,%2,%3};"
        : "+f"(d[0]), "+f"(d[1]), "+f"(d[2]), "+f"(d[3])
        : "r"(a[0]), "r"(a[1]), "r"(a[2]), "r"(a[3]), "r"(b[0]), "r"(b[1]));
}

// ---------------- convert kernels (MLP=4; grid*CNVT*4 == n4 exactly) -----------
__global__ void conv_X_kernel(const float4* __restrict__ src, long n4) {
    uint2* __restrict__ dst = reinterpret_cast<uint2*>(g_Xh);
    const long base = (long)blockIdx.x * (CNVT * 4) + threadIdx.x;
    float4 v[4];
#pragma unroll
    for (int k = 0; k < 4; ++k) v[k] = src[base + k * CNVT];
#pragma unroll
    for (int k = 0; k < 4; ++k) {
        __half2 h0 = __floats2half2_rn(v[k].x, v[k].y);
        __half2 h1 = __floats2half2_rn(v[k].z, v[k].w);
        dst[base + k * CNVT] = make_uint2(*(uint32_t*)&h0, *(uint32_t*)&h1);
    }
}
__global__ void conv_W_kernel(const float4* __restrict__ src, long n4) {
    uint2* __restrict__ dst = reinterpret_cast<uint2*>(g_Wh);
    const long base = (long)blockIdx.x * (CNVT * 4) + threadIdx.x;
    float4 v[4];
#pragma unroll
    for (int k = 0; k < 4; ++k) v[k] = src[base + k * CNVT];
#pragma unroll
    for (int k = 0; k < 4; ++k) {
        __half2 h0 = __floats2half2_rn(v[k].x, v[k].y);
        __half2 h1 = __floats2half2_rn(v[k].z, v[k].w);
        dst[base + k * CNVT] = make_uint2(*(uint32_t*)&h0, *(uint32_t*)&h1);
    }
}

// ---------------- GEMM ----------------------------------------------------------
__global__ __launch_bounds__(NTHR, 3)
void gemm_f16_kernel(const float* __restrict__ Bv,
                     float* __restrict__ O,
                     int T, int V, int K) {
    extern __shared__ char smem[];
    const uint32_t sbase = smem_u32_of(smem);

    const int tid  = threadIdx.x;
    const int wid  = tid >> 5;      // 0..3 -> m-group of 32 rows; all warps span n=64
    const int lane = tid & 31;
    const int mtile = blockIdx.x;
    const int ntile = blockIdx.y;

    // ---- staging (128 thr): A = 128 rows x 4 segs (4/thread), B = 64 x 4 (2/thread)
    const int srow = tid >> 2;           // 0..31
    const int seg  = tid & 3;            // 16B segment within 32-half row
    const __half* gA = g_Xh + (size_t)(mtile * BM + srow) * K + seg * 8;
    const __half* gB = g_Wh + (size_t)(ntile * BN + srow) * K + seg * 8;
    const uint32_t sdstA = (uint32_t)(srow * (TS * 2) + seg * 16);
    const uint32_t sdstB = sdstA;

    // ---- ldmatrix per-lane base offsets (bytes, relative to tile bases) ----
    const int a_row = wid * 32 + (lane & 7) + ((lane >> 3) & 1) * 8;
    const uint32_t a_off = (uint32_t)(a_row * (TS * 2) + (lane >> 4) * 16);
    const int b_row = (lane & 7) + ((lane >> 4) & 1) * 8;
    const uint32_t b_off = (uint32_t)(b_row * (TS * 2) + ((lane >> 3) & 1) * 16);

    float acc[2][8][4];
#pragma unroll
    for (int i = 0; i < 2; ++i)
#pragma unroll
        for (int j = 0; j < 8; ++j)
#pragma unroll
            for (int c = 0; c < 4; ++c) acc[i][j][c] = 0.f;

    const int KT = K / BK;  // 128

    auto issue_stage = [&](int t) {
        const uint32_t st = sbase + (uint32_t)(t % STAGES) * STAGE_BYTES;
        const size_t kb = (size_t)t * BK;
#pragma unroll
        for (int i = 0; i < 4; ++i)   // A rows srow, srow+32, srow+64, srow+96
            cp_async16(st + sdstA + (uint32_t)(i * 32 * (TS * 2)),
                       gA + kb + (size_t)(i * 32) * K);
#pragma unroll
        for (int i = 0; i < 2; ++i)   // B rows srow, srow+32
            cp_async16(st + TILE_A_BYTES + sdstB + (uint32_t)(i * 32 * (TS * 2)),
                       gB + kb + (size_t)(i * 32) * K);
        asm volatile("cp.async.commit_group;" ::: "memory");
    };

    issue_stage(0);
    issue_stage(1);
    issue_stage(2);

    for (int t = 0; t < KT; ++t) {
        asm volatile("cp.async.wait_group 2;" ::: "memory");
        __syncthreads();   // stage t visible; all threads past iter t-1 reads
                           // -> safe to overwrite slot (t+3)%4 == (t-1)%4
        if (t + 3 < KT) issue_stage(t + 3);

        const uint32_t st = sbase + (uint32_t)(t % STAGES) * STAGE_BYTES;
        const uint32_t aAdr = st + a_off;
        const uint32_t bAdr = st + TILE_A_BYTES + b_off;

        // ---- hoisted fragment loads: all 8 LDSM.x4 for BOTH ks issue first,
        //      so their latency overlaps the HMMA stream below.
        uint32_t af[2][2][4];   // [ks][m16-tile][4]
        uint32_t bf[2][4][4];   // [ks][n16-pair][4]
#pragma unroll
        for (int ks = 0; ks < 2; ++ks) {
            const uint32_t koff = (uint32_t)(ks * 32);  // 16 halfs = 32B
            ldmatrix_x4(af[ks][0][0], af[ks][0][1], af[ks][0][2], af[ks][0][3],
                        aAdr + koff);
            ldmatrix_x4(af[ks][1][0], af[ks][1][1], af[ks][1][2], af[ks][1][3],
                        aAdr + koff + 16 * (TS * 2));
#pragma unroll
            for (int jp = 0; jp < 4; ++jp)
                ldmatrix_x4(bf[ks][jp][0], bf[ks][jp][1],
                            bf[ks][jp][2], bf[ks][jp][3],
                            bAdr + koff + (uint32_t)(jp * 16 * (TS * 2)));
        }

#pragma unroll
        for (int ks = 0; ks < 2; ++ks)
#pragma unroll
            for (int im = 0; im < 2; ++im)
#pragma unroll
                for (int jn = 0; jn < 8; ++jn) {
                    uint32_t breg[2] = { bf[ks][jn >> 1][(jn & 1) * 2],
                                         bf[ks][jn >> 1][(jn & 1) * 2 + 1] };
                    mma_f16(acc[im][jn], af[ks][im], breg);
                }
        // single sync per iter: next leading barrier protects slot reuse.
    }

    // ---- epilogue: bias + store (warp covers rows wid*32..+31, all 64 cols) ----
    const int r_base = mtile * BM + wid * 32 + (lane >> 2);
    const int c_base = ntile * BN + (lane & 3) * 2;
#pragma unroll
    for (int im = 0; im < 2; ++im) {
#pragma unroll
        for (int jn = 0; jn < 8; ++jn) {
            const int col = c_base + jn * 8;
            const float2 bv = *reinterpret_cast<const float2*>(Bv + col);
            const int r0 = r_base + im * 16;
            float2 o0 = make_float2(acc[im][jn][0] + bv.x, acc[im][jn][1] + bv.y);
            float2 o1 = make_float2(acc[im][jn][2] + bv.x, acc[im][jn][3] + bv.y);
            *reinterpret_cast<float2*>(O + (size_t)r0 * V + col)       = o0;
            *reinterpret_cast<float2*>(O + (size_t)(r0 + 8) * V + col) = o1;
        }
    }
}

// ---------------- launch --------------------------------------------------------
extern "C" void kernel_launch(void* const* d_in, const int* in_sizes, int n_in,
                              void* d_out, int out_size) {
    const float* X  = (const float*)d_in[0];  // [T, D]
    const float* W  = (const float*)d_in[1];  // [V, D]
    const float* Bv = (const float*)d_in[2];  // [V]
    float* O = (float*)d_out;                 // [T, V]

    const int V = in_sizes[2];
    const int D = in_sizes[1] / V;
    const int T = in_sizes[0] / D;

    const long nx4 = (long)T * D / 4;
    const long nw4 = (long)V * D / 4;
    conv_W_kernel<<<(unsigned)(nw4 / (CNVT * 4)), CNVT>>>((const float4*)W, nw4);
    conv_X_kernel<<<(unsigned)(nx4 / (CNVT * 4)), CNVT>>>((const float4*)X, nx4);

    cudaFuncSetAttribute(gemm_f16_kernel,
                         cudaFuncAttributeMaxDynamicSharedMemorySize, SMEM_NEED);
    dim3 grid(T / BM, V / BN);  // (16, 500); x fastest -> W tile reuse in L2
    gemm_f16_kernel<<<grid, NTHR, SMEM_NEED>>>(Bv, O, T, V, D);
}